// round 7
// baseline (speedup 1.0000x reference)
#include <cuda_runtime.h>
#include <cstdint>

// Graph unpooling: out[dst] += edge_attr * x[src]
//   x [50000,128] f32, src/dst [E=800000] i32, edge_attr [E] f32, out [200000,128] f32
// Per-call dst-CSR (hist -> single-pass lookback scan -> fill), then
// warp-per-node register accumulation with one streaming store.

#define MAXN   200704
#define MAXE   800000
#define SCAN_B 1024
#define NBLK_MAX 256

__device__ int  g_count[MAXN];     // per-node edge count
__device__ int2 g_meta[MAXN];      // {segment start, count}
__device__ int  g_cursor[MAXN];    // running fill position
__device__ int2 g_edges[MAXE];     // CSR payload: {src, bitcast(weight)}

// decoupled-lookback state
__device__ int           g_ticket;
__device__ volatile int  g_flag[NBLK_MAX];     // 0=invalid 1=aggregate 2=prefix
__device__ volatile int  g_aggr[NBLK_MAX];
__device__ volatile int  g_pfx[NBLK_MAX];

__global__ void k_reset(int n, int nb) {
    int i = blockIdx.x * blockDim.x + threadIdx.x;
    if (i < n) g_count[i] = 0;
    if (i < nb) g_flag[i] = 0;
    if (i == 0) g_ticket = 0;
}

// Scalar: one edge per thread, huge grid = max warp-level parallelism
__global__ void k_hist(const int* __restrict__ dst, int E) {
    int e = blockIdx.x * blockDim.x + threadIdx.x;
    if (e < E) atomicAdd(&g_count[dst[e]], 1);
}

// Single-pass scan with decoupled lookback; atomic ticket orders blocks.
__global__ void __launch_bounds__(SCAN_B)
k_scan(int n) {
    __shared__ int swarp[32];
    __shared__ int sbid, sbase;
    int t = threadIdx.x, lane = t & 31, wid = t >> 5;

    if (t == 0) sbid = atomicAdd(&g_ticket, 1);
    __syncthreads();
    int bid = sbid;
    int i = bid * SCAN_B + t;
    int c = (i < n) ? g_count[i] : 0;

    int v = c;
    #pragma unroll
    for (int off = 1; off < 32; off <<= 1) {
        int u = __shfl_up_sync(0xffffffffu, v, off);
        if (lane >= off) v += u;
    }
    if (lane == 31) swarp[wid] = v;
    __syncthreads();
    if (wid == 0) {
        int w = swarp[lane];
        #pragma unroll
        for (int off = 1; off < 32; off <<= 1) {
            int u = __shfl_up_sync(0xffffffffu, w, off);
            if (lane >= off) w += u;
        }
        swarp[lane] = w;
    }
    __syncthreads();
    int incl  = v + (wid > 0 ? swarp[wid - 1] : 0);
    int total = swarp[31];

    if (t == 0) {
        if (bid == 0) {
            g_pfx[0] = total; __threadfence(); g_flag[0] = 2;
            sbase = 0;
        } else {
            g_aggr[bid] = total; __threadfence(); g_flag[bid] = 1;
            int base = 0;
            for (int j = bid - 1; j >= 0; j--) {
                int f;
                while ((f = g_flag[j]) == 0) { }
                if (f == 2) { base += g_pfx[j]; break; }
                base += g_aggr[j];
            }
            g_pfx[bid] = base + total; __threadfence(); g_flag[bid] = 2;
            sbase = base;
        }
    }
    __syncthreads();

    if (i < n) {
        int st = sbase + incl - c;
        g_meta[i]   = make_int2(st, c);
        g_cursor[i] = st;
    }
}

// Scalar: one edge per thread
__global__ void k_fill(const int* __restrict__ src, const int* __restrict__ dst,
                       const float* __restrict__ attr, int E) {
    int e = blockIdx.x * blockDim.x + threadIdx.x;
    if (e >= E) return;
    int pos = atomicAdd(&g_cursor[dst[e]], 1);
    g_edges[pos] = make_int2(src[e], __float_as_int(attr[e]));
}

// One warp per fine node: 2-deep load pipeline (matches avg fan-in 4),
// register accumulate, single streaming store (keeps x resident in L2).
__global__ void __launch_bounds__(256)
k_gather(const float4* __restrict__ x4, float4* __restrict__ out4, int n) {
    int gtid = blockIdx.x * blockDim.x + threadIdx.x;
    int node = gtid >> 5;
    int lane = gtid & 31;
    if (node >= n) return;

    int2 mc  = __ldg(&g_meta[node]);
    int  beg = mc.x, cnt = mc.y;

    float4 acc = make_float4(0.f, 0.f, 0.f, 0.f);
    int k = 0;
    for (; k + 1 < cnt; k += 2) {
        int2 e0 = __ldg(&g_edges[beg + k]);
        int2 e1 = __ldg(&g_edges[beg + k + 1]);
        float4 v0 = __ldg(&x4[(size_t)e0.x * 32 + lane]);
        float4 v1 = __ldg(&x4[(size_t)e1.x * 32 + lane]);
        float w0 = __int_as_float(e0.y);
        float w1 = __int_as_float(e1.y);
        acc.x += w0 * v0.x; acc.y += w0 * v0.y; acc.z += w0 * v0.z; acc.w += w0 * v0.w;
        acc.x += w1 * v1.x; acc.y += w1 * v1.y; acc.z += w1 * v1.z; acc.w += w1 * v1.w;
    }
    if (k < cnt) {
        int2 e0 = __ldg(&g_edges[beg + k]);
        float4 v0 = __ldg(&x4[(size_t)e0.x * 32 + lane]);
        float w0 = __int_as_float(e0.y);
        acc.x += w0 * v0.x; acc.y += w0 * v0.y; acc.z += w0 * v0.z; acc.w += w0 * v0.w;
    }
    __stcs(&out4[(size_t)node * 32 + lane], acc);
}

extern "C" void kernel_launch(void* const* d_in, const int* in_sizes, int n_in,
                              void* d_out, int out_size) {
    const float4* x4   = (const float4*)d_in[0];
    const int*    src  = (const int*)d_in[1];
    const int*    dst  = (const int*)d_in[2];
    const float*  attr = (const float*)d_in[3];
    float4*       out4 = (float4*)d_out;

    int E  = in_sizes[1];
    int n  = out_size / 128;                 // fine nodes (C=128)
    int nb = (n + SCAN_B - 1) / SCAN_B;      // scan blocks (<= NBLK_MAX)

    int tb = 256;
    k_reset<<<(n + tb - 1) / tb, tb>>>(n, nb);
    k_hist <<<(E + tb - 1) / tb, tb>>>(dst, E);
    k_scan <<<nb, SCAN_B>>>(n);
    k_fill <<<(E + tb - 1) / tb, tb>>>(src, dst, attr, E);

    long long gt = (long long)n * 32;
    k_gather<<<(int)((gt + tb - 1) / tb), tb>>>(x4, out4, n);
}

// round 8
// speedup vs baseline: 1.1159x; 1.1159x over previous
#include <cuda_runtime.h>
#include <cstdint>

// Graph unpooling: out[dst] += edge_attr * x[src]
//   x [50000,128] f32, src/dst [E=800000] i32, edge_attr [E] f32, out [200000,128] f32
// Per-call dst-CSR (hist -> single-pass warp-lookback scan -> fill), then
// warp-per-node register accumulation with one streaming store.

#define MAXN   200704
#define MAXE   800000
#define SCAN_B 1024
#define NBLK_MAX 256

__device__ int  g_count[MAXN];     // per-node edge count
__device__ int2 g_meta[MAXN];      // {segment start, count}
__device__ int  g_cursor[MAXN];    // running fill position
__device__ int2 g_edges[MAXE];     // CSR payload: {src, bitcast(weight)}

// decoupled-lookback state
__device__ int           g_ticket;
__device__ volatile int  g_flag[NBLK_MAX];     // 0=invalid 1=aggregate 2=prefix
__device__ volatile int  g_aggr[NBLK_MAX];
__device__ volatile int  g_pfx[NBLK_MAX];

__global__ void k_reset(int n, int nb) {
    int i = blockIdx.x * blockDim.x + threadIdx.x;
    if (i < n) g_count[i] = 0;
    if (i < nb) g_flag[i] = 0;
    if (i == 0) g_ticket = 0;
}

// Scalar: one edge per thread, huge grid = max warp-level parallelism
__global__ void k_hist(const int* __restrict__ dst, int E) {
    int e = blockIdx.x * blockDim.x + threadIdx.x;
    if (e < E) atomicAdd(&g_count[dst[e]], 1);
}

// Single-pass scan, warp-parallel decoupled lookback (32 predecessors/round).
__global__ void __launch_bounds__(SCAN_B)
k_scan(int n) {
    __shared__ int swarp[32];
    __shared__ int sbid, sbase;
    int t = threadIdx.x, lane = t & 31, wid = t >> 5;

    if (t == 0) sbid = atomicAdd(&g_ticket, 1);
    __syncthreads();
    int bid = sbid;
    int i = bid * SCAN_B + t;
    int c = (i < n) ? g_count[i] : 0;

    // block inclusive scan via shfl
    int v = c;
    #pragma unroll
    for (int off = 1; off < 32; off <<= 1) {
        int u = __shfl_up_sync(0xffffffffu, v, off);
        if (lane >= off) v += u;
    }
    if (lane == 31) swarp[wid] = v;
    __syncthreads();
    if (wid == 0) {
        int w = swarp[lane];
        #pragma unroll
        for (int off = 1; off < 32; off <<= 1) {
            int u = __shfl_up_sync(0xffffffffu, w, off);
            if (lane >= off) w += u;
        }
        swarp[lane] = w;
    }
    __syncthreads();
    int incl  = v + (wid > 0 ? swarp[wid - 1] : 0);
    int total = swarp[31];

    // warp 0: publish aggregate, then warp-parallel lookback, publish prefix
    if (wid == 0) {
        if (bid == 0) {
            if (lane == 0) {
                g_pfx[0] = total; __threadfence(); g_flag[0] = 2;
                sbase = 0;
            }
        } else {
            if (lane == 0) {
                g_aggr[bid] = total; __threadfence(); g_flag[bid] = 1;
            }
            int base = 0;
            for (int win = bid - 1; win >= 0; win -= 32) {
                int j = win - lane;            // lane 0 = nearest predecessor
                int f = 0, val = 0;
                if (j >= 0) {
                    while ((f = g_flag[j]) == 0) { }
                    val = (f == 2) ? g_pfx[j] : g_aggr[j];
                }
                unsigned pmask = __ballot_sync(0xffffffffu, (j >= 0) && (f == 2));
                int cut = pmask ? (__ffs(pmask) - 1) : 32;  // nearest prefix lane
                int contrib = (j >= 0 && lane <= cut) ? val : 0;
                #pragma unroll
                for (int off = 16; off; off >>= 1)
                    contrib += __shfl_down_sync(0xffffffffu, contrib, off);
                if (lane == 0) base += contrib;
                if (pmask) break;              // found an inclusive prefix
            }
            if (lane == 0) {
                g_pfx[bid] = base + total; __threadfence(); g_flag[bid] = 2;
                sbase = base;
            }
        }
    }
    __syncthreads();

    if (i < n) {
        int st = sbase + incl - c;
        g_meta[i]   = make_int2(st, c);
        g_cursor[i] = st;
    }
}

// Scalar: one edge per thread
__global__ void k_fill(const int* __restrict__ src, const int* __restrict__ dst,
                       const float* __restrict__ attr, int E) {
    int e = blockIdx.x * blockDim.x + threadIdx.x;
    if (e >= E) return;
    int pos = atomicAdd(&g_cursor[dst[e]], 1);
    g_edges[pos] = make_int2(src[e], __float_as_int(attr[e]));
}

// One warp per fine node: 2-deep load pipeline (matches avg fan-in 4),
// register accumulate, single streaming store (keeps x resident in L2).
__global__ void __launch_bounds__(256)
k_gather(const float4* __restrict__ x4, float4* __restrict__ out4, int n) {
    int gtid = blockIdx.x * blockDim.x + threadIdx.x;
    int node = gtid >> 5;
    int lane = gtid & 31;
    if (node >= n) return;

    int2 mc  = __ldg(&g_meta[node]);
    int  beg = mc.x, cnt = mc.y;

    float4 acc = make_float4(0.f, 0.f, 0.f, 0.f);
    int k = 0;
    for (; k + 1 < cnt; k += 2) {
        int2 e0 = __ldg(&g_edges[beg + k]);
        int2 e1 = __ldg(&g_edges[beg + k + 1]);
        float4 v0 = __ldg(&x4[(size_t)e0.x * 32 + lane]);
        float4 v1 = __ldg(&x4[(size_t)e1.x * 32 + lane]);
        float w0 = __int_as_float(e0.y);
        float w1 = __int_as_float(e1.y);
        acc.x += w0 * v0.x; acc.y += w0 * v0.y; acc.z += w0 * v0.z; acc.w += w0 * v0.w;
        acc.x += w1 * v1.x; acc.y += w1 * v1.y; acc.z += w1 * v1.z; acc.w += w1 * v1.w;
    }
    if (k < cnt) {
        int2 e0 = __ldg(&g_edges[beg + k]);
        float4 v0 = __ldg(&x4[(size_t)e0.x * 32 + lane]);
        float w0 = __int_as_float(e0.y);
        acc.x += w0 * v0.x; acc.y += w0 * v0.y; acc.z += w0 * v0.z; acc.w += w0 * v0.w;
    }
    __stcs(&out4[(size_t)node * 32 + lane], acc);
}

extern "C" void kernel_launch(void* const* d_in, const int* in_sizes, int n_in,
                              void* d_out, int out_size) {
    const float4* x4   = (const float4*)d_in[0];
    const int*    src  = (const int*)d_in[1];
    const int*    dst  = (const int*)d_in[2];
    const float*  attr = (const float*)d_in[3];
    float4*       out4 = (float4*)d_out;

    int E  = in_sizes[1];
    int n  = out_size / 128;                 // fine nodes (C=128)
    int nb = (n + SCAN_B - 1) / SCAN_B;      // scan blocks (<= NBLK_MAX)

    int tb = 256;
    k_reset<<<(n + tb - 1) / tb, tb>>>(n, nb);
    k_hist <<<(E + tb - 1) / tb, tb>>>(dst, E);
    k_scan <<<nb, SCAN_B>>>(n);
    k_fill <<<(E + tb - 1) / tb, tb>>>(src, dst, attr, E);

    long long gt = (long long)n * 32;
    k_gather<<<(int)((gt + tb - 1) / tb), tb>>>(x4, out4, n);
}